// round 2
// baseline (speedup 1.0000x reference)
#include <cuda_runtime.h>

// idf-weighted masked mean pooling:
//   out[b,d] = sum_l hidden[b,l,d] * (mask[b,l] ? idf[ids[b,l]] : 0) / max(sum_l mask[b,l], 1e-9)
// hidden [4096, 100, 768] fp32 — 1.26 GB streamed once; pure HBM-bound.
#define B_SZ   4096
#define L_SZ   100
#define D_SZ   768
#define THREADS 192          // D/4 float4 lanes
#define GRID   (148 * 8)     // persistent: exactly one full wave at occ=8

__global__ __launch_bounds__(THREADS, 8)
void sbert_idf_pool_kernel(const float* __restrict__ hidden,
                           const int*   __restrict__ ids,
                           const int*   __restrict__ mask,
                           const float* __restrict__ idf,
                           float*       __restrict__ out) {
    __shared__ float wm[2][L_SZ];

    const int tid = threadIdx.x;
    int p = 0;

    for (int b = blockIdx.x; b < B_SZ; b += GRID, p ^= 1) {
        // ---- prologue: per-token weight gather + mask popcount ------------
        int m = 0;
        if (tid < L_SZ) {
            m = __ldg(&mask[b * L_SZ + tid]);
            float w = 0.0f;
            if (m != 0) {
                w = __ldg(&idf[__ldg(&ids[b * L_SZ + tid])]);
            }
            wm[p][tid] = w;
        }
        // barrier + block-wide popcount in one instruction
        int nmask = __syncthreads_count(m != 0);
        float inv = 1.0f / fmaxf((float)nmask, 1e-9f);

        // ---- mainloop: stream 100 x 3072B contiguous rows, float4 ---------
        const float4* __restrict__ h =
            reinterpret_cast<const float4*>(hidden + (long long)b * (L_SZ * D_SZ)) + tid;

        float4 a0 = make_float4(0.f, 0.f, 0.f, 0.f);
        float4 a1 = a0, a2 = a0, a3 = a0;

        #pragma unroll 5
        for (int l = 0; l < L_SZ; l += 4) {
            const float w0 = wm[p][l + 0];
            const float w1 = wm[p][l + 1];
            const float w2 = wm[p][l + 2];
            const float w3 = wm[p][l + 3];
            // evict-first streaming loads: hidden has zero reuse, keep L2 clean
            const float4 h0 = __ldcs(&h[(l + 0) * (D_SZ / 4)]);
            const float4 h1 = __ldcs(&h[(l + 1) * (D_SZ / 4)]);
            const float4 h2 = __ldcs(&h[(l + 2) * (D_SZ / 4)]);
            const float4 h3 = __ldcs(&h[(l + 3) * (D_SZ / 4)]);
            a0.x = fmaf(h0.x, w0, a0.x); a0.y = fmaf(h0.y, w0, a0.y);
            a0.z = fmaf(h0.z, w0, a0.z); a0.w = fmaf(h0.w, w0, a0.w);
            a1.x = fmaf(h1.x, w1, a1.x); a1.y = fmaf(h1.y, w1, a1.y);
            a1.z = fmaf(h1.z, w1, a1.z); a1.w = fmaf(h1.w, w1, a1.w);
            a2.x = fmaf(h2.x, w2, a2.x); a2.y = fmaf(h2.y, w2, a2.y);
            a2.z = fmaf(h2.z, w2, a2.z); a2.w = fmaf(h2.w, w2, a2.w);
            a3.x = fmaf(h3.x, w3, a3.x); a3.y = fmaf(h3.y, w3, a3.y);
            a3.z = fmaf(h3.z, w3, a3.z); a3.w = fmaf(h3.w, w3, a3.w);
        }

        float4 r;
        r.x = (a0.x + a1.x + a2.x + a3.x) * inv;
        r.y = (a0.y + a1.y + a2.y + a3.y) * inv;
        r.z = (a0.z + a1.z + a2.z + a3.z) * inv;
        r.w = (a0.w + a1.w + a2.w + a3.w) * inv;

        reinterpret_cast<float4*>(out)[b * (D_SZ / 4) + tid] = r;
        // no trailing barrier needed: next row writes wm[p^1] (double-buffered)
    }
}

extern "C" void kernel_launch(void* const* d_in, const int* in_sizes, int n_in,
                              void* d_out, int out_size) {
    const float* hidden = (const float*)d_in[0];
    const int*   ids    = (const int*)  d_in[1];
    const int*   mask   = (const int*)  d_in[2];
    const float* idf    = (const float*)d_in[3];
    float*       out    = (float*)d_out;

    sbert_idf_pool_kernel<<<GRID, THREADS>>>(hidden, ids, mask, idf, out);
}

// round 4
// speedup vs baseline: 1.0363x; 1.0363x over previous
#include <cuda_runtime.h>

// idf-weighted masked mean pooling:
//   out[b,d] = sum_l hidden[b,l,d] * (mask[b,l] ? idf[ids[b,l]] : 0) / max(sum_l mask[b,l], 1e-9)
// hidden [4096, 100, 768] fp32 — 1.26 GB streamed once; pure HBM-bound.
#define B_SZ   4096
#define L_SZ   100
#define D_SZ   768
#define THREADS 192   // D/4 float4 lanes
#define STRIDE  (D_SZ / 4)

__global__ __launch_bounds__(THREADS, 8)
void sbert_idf_pool_kernel(const float* __restrict__ hidden,
                           const int*   __restrict__ ids,
                           const int*   __restrict__ mask,
                           const float* __restrict__ idf,
                           float*       __restrict__ out) {
    __shared__ float wm[L_SZ];

    const int b   = blockIdx.x;
    const int tid = threadIdx.x;

    // ---- issue the long-pole gather chain AND the first stream loads
    //      before any barrier, so the memory pipe is busy from cycle 0 ------
    int m = 0, id = 0;
    if (tid < L_SZ) {
        m  = mask[b * L_SZ + tid];
        id = ids [b * L_SZ + tid];
    }

    const float4* __restrict__ h =
        reinterpret_cast<const float4*>(hidden + (long long)b * (L_SZ * D_SZ)) + tid;

    // peeled first 4 row loads — independent of the weight gather
    const float4 h0 = h[0 * STRIDE];
    const float4 h1 = h[1 * STRIDE];
    const float4 h2 = h[2 * STRIDE];
    const float4 h3 = h[3 * STRIDE];

    // dependent idf gather overlaps with the loads above
    float w = 0.0f;
    if (tid < L_SZ) {
        if (m != 0) w = __ldg(&idf[id]);
        wm[tid] = w;
    }
    // barrier + block-wide mask popcount in one instruction
    int nmask = __syncthreads_count(m != 0);
    float inv = 1.0f / fmaxf((float)nmask, 1e-9f);

    // ---- peeled accumulation ---------------------------------------------
    float4 a0, a1, a2, a3;
    {
        const float w0 = wm[0], w1 = wm[1], w2 = wm[2], w3 = wm[3];
        a0.x = h0.x * w0; a0.y = h0.y * w0; a0.z = h0.z * w0; a0.w = h0.w * w0;
        a1.x = h1.x * w1; a1.y = h1.y * w1; a1.z = h1.z * w1; a1.w = h1.w * w1;
        a2.x = h2.x * w2; a2.y = h2.y * w2; a2.z = h2.z * w2; a2.w = h2.w * w2;
        a3.x = h3.x * w3; a3.y = h3.y * w3; a3.z = h3.z * w3; a3.w = h3.w * w3;
    }

    // ---- mainloop: remaining 96 rows, fully unrolled (max load batching) --
    #pragma unroll
    for (int l = 4; l < L_SZ; l += 4) {
        const float w0 = wm[l + 0];
        const float w1 = wm[l + 1];
        const float w2 = wm[l + 2];
        const float w3 = wm[l + 3];
        const float4 g0 = h[(l + 0) * STRIDE];
        const float4 g1 = h[(l + 1) * STRIDE];
        const float4 g2 = h[(l + 2) * STRIDE];
        const float4 g3 = h[(l + 3) * STRIDE];
        a0.x = fmaf(g0.x, w0, a0.x); a0.y = fmaf(g0.y, w0, a0.y);
        a0.z = fmaf(g0.z, w0, a0.z); a0.w = fmaf(g0.w, w0, a0.w);
        a1.x = fmaf(g1.x, w1, a1.x); a1.y = fmaf(g1.y, w1, a1.y);
        a1.z = fmaf(g1.z, w1, a1.z); a1.w = fmaf(g1.w, w1, a1.w);
        a2.x = fmaf(g2.x, w2, a2.x); a2.y = fmaf(g2.y, w2, a2.y);
        a2.z = fmaf(g2.z, w2, a2.z); a2.w = fmaf(g2.w, w2, a2.w);
        a3.x = fmaf(g3.x, w3, a3.x); a3.y = fmaf(g3.y, w3, a3.y);
        a3.z = fmaf(g3.z, w3, a3.z); a3.w = fmaf(g3.w, w3, a3.w);
    }

    float4 r;
    r.x = (a0.x + a1.x + a2.x + a3.x) * inv;
    r.y = (a0.y + a1.y + a2.y + a3.y) * inv;
    r.z = (a0.z + a1.z + a2.z + a3.z) * inv;
    r.w = (a0.w + a1.w + a2.w + a3.w) * inv;

    reinterpret_cast<float4*>(out)[b * STRIDE + tid] = r;
}

extern "C" void kernel_launch(void* const* d_in, const int* in_sizes, int n_in,
                              void* d_out, int out_size) {
    const float* hidden = (const float*)d_in[0];
    const int*   ids    = (const int*)  d_in[1];
    const int*   mask   = (const int*)  d_in[2];
    const float* idf    = (const float*)d_in[3];
    float*       out    = (float*)d_out;

    sbert_idf_pool_kernel<<<B_SZ, THREADS>>>(hidden, ids, mask, idf, out);
}